// round 9
// baseline (speedup 1.0000x reference)
#include <cuda_runtime.h>
#include <cstdint>

// StateDecoder: out[b, r, c] = (x[b, c] >> r) & 1 as float32.
// B = 2048, C = 2048, R = 32. 16 MiB in, 512 MiB out.
//
// Converged design: this kernel is HBM write-bound at the measured ~6.0 TB/s
// pure-write ceiling (75% DRAM busy; STG/stcs/TMA/evict-policy all identical).
// Final form = minimal overhead: one block per batch row, 2 int4 per thread
// at c-offsets j and j+1024 so every warp STG.128 group is a contiguous 512B
// span (full-line writes), plain cache policy, no smem/barriers.

#define BATCH 2048
#define NUM_CANDIDATES 2048
#define NUM_REPLICAS 32

__device__ __forceinline__ float4 bits_to_f4(int4 v, int r) {
    // bit -> 0x00000000 or 0x3F800000 (1.0f) without I2F
    unsigned f0 = (0u - (((unsigned)v.x >> r) & 1u)) & 0x3F800000u;
    unsigned f1 = (0u - (((unsigned)v.y >> r) & 1u)) & 0x3F800000u;
    unsigned f2 = (0u - (((unsigned)v.z >> r) & 1u)) & 0x3F800000u;
    unsigned f3 = (0u - (((unsigned)v.w >> r) & 1u)) & 0x3F800000u;
    float4 f;
    f.x = __uint_as_float(f0);
    f.y = __uint_as_float(f1);
    f.z = __uint_as_float(f2);
    f.w = __uint_as_float(f3);
    return f;
}

__global__ __launch_bounds__(256) void state_decoder_kernel(
    const int4* __restrict__ x4,   // [B * C/4]
    float4* __restrict__ out4      // [B * R * C/4]
) {
    constexpr int C4 = NUM_CANDIDATES / 4;   // 512 chunks per row
    constexpr int HALF = C4 / 2;             // 256

    const int b = blockIdx.x;
    const int j = threadIdx.x;               // 0..255 -> chunks j and j+HALF

    const int4 va = x4[(size_t)b * C4 + j];
    const int4 vb = x4[(size_t)b * C4 + j + HALF];

    float4* dst = out4 + (size_t)b * (NUM_REPLICAS * C4) + j;

    #pragma unroll
    for (int r = 0; r < NUM_REPLICAS; ++r) {
        dst[(size_t)r * C4]        = bits_to_f4(va, r);
        dst[(size_t)r * C4 + HALF] = bits_to_f4(vb, r);
    }
}

extern "C" void kernel_launch(void* const* d_in, const int* in_sizes, int n_in,
                              void* d_out, int out_size) {
    const int4* x4 = (const int4*)d_in[0];
    float4* out4 = (float4*)d_out;

    state_decoder_kernel<<<BATCH, 256>>>(x4, out4);
}